// round 1
// baseline (speedup 1.0000x reference)
#include <cuda_runtime.h>
#include <math.h>

// Problem constants (fixed by the reference):
//   BATCH=128, SEQ_LEN=4096, HIDDEN=512, WINDOW=7 (W2=49), GRID=256
#define HIDDEN   512
#define WINDOW   7
#define W2       (WINDOW * WINDOW)
#define NTHREADS 512
#define NWARPS   (NTHREADS / 32)

__global__ __launch_bounds__(NTHREADS, 2)
void hilbert_attn_kernel(const float* __restrict__ q,      // (B,1,H)
                         const float* __restrict__ k,      // (B,S,H)
                         const float* __restrict__ v,      // (B,S,H)
                         const int*   __restrict__ qpos,   // (B,)
                         const float* __restrict__ dscale, // ()
                         const float* __restrict__ lbias,  // (W2,)
                         const int*   __restrict__ hcoords,// (MAX_SEQ,2)
                         const int*   __restrict__ hinv,   // (GRID,GRID)
                         float*       __restrict__ out,    // (B,H)
                         int S, int grid_n)
{
    const int b    = blockIdx.x;
    const int tid  = threadIdx.x;
    const int wid  = tid >> 5;
    const int lane = tid & 31;

    __shared__ float s_q[HIDDEN];
    __shared__ int   s_pos[W2];     // -1 if invalid
    __shared__ float s_logw[W2];
    __shared__ float s_score[W2];
    __shared__ float s_attn[W2];
    __shared__ int   s_q2d[2];

    // --- stage 0: query coords + q vector into shared ---
    if (tid == 0) {
        int p = qpos[b];
        s_q2d[0] = hcoords[2 * p];
        s_q2d[1] = hcoords[2 * p + 1];
    }
    s_q[tid] = q[(size_t)b * HIDDEN + tid];
    __syncthreads();

    // --- stage 1: 49 neighbor positions in parallel ---
    if (tid < W2) {
        int dx = tid / WINDOW - (WINDOW / 2);
        int dy = tid % WINDOW - (WINDOW / 2);
        int nx = s_q2d[0] + dx;
        int ny = s_q2d[1] + dy;
        bool ing = (nx >= 0) & (nx < grid_n) & (ny >= 0) & (ny < grid_n);
        int pos = 0;
        if (ing) pos = hinv[nx * grid_n + ny];
        bool valid = ing && (pos < S) && (pos >= 0);
        s_pos[tid] = valid ? pos : -1;
    }
    __syncthreads();

    // --- stage 2: serial cumsum (compacted bias index) + logw, thread 0 ---
    if (tid == 0) {
        float scale = dscale[0];
        int c = 0;
        #pragma unroll
        for (int w = 0; w < W2; ++w) {
            int dx = w / WINDOW - (WINDOW / 2);
            int dy = w % WINDOW - (WINDOW / 2);
            if (s_pos[w] >= 0) {
                float bias = lbias[c];
                ++c;
                float dist = (float)(abs(dx) + abs(dy));
                float ww = __expf(-dist * scale) + bias;
                s_logw[w] = logf(ww + 1e-8f);
            } else {
                s_logw[w] = 0.0f;
            }
        }
    }
    __syncthreads();

    // --- stage 3: scores. Warp `wid` handles windows wid, wid+16, wid+32 ---
    const float inv_sqrt_h = 0.04419417382415922f; // 1/sqrt(512)
    const float4* qq = reinterpret_cast<const float4*>(s_q);
    for (int w = wid; w < W2; w += NWARPS) {
        int pos = s_pos[w];
        float acc = 0.0f;
        if (pos >= 0) {
            const float4* kk = reinterpret_cast<const float4*>(
                k + (size_t)b * S * HIDDEN + (size_t)pos * HIDDEN);
            #pragma unroll
            for (int i = 0; i < HIDDEN / 4 / 32; ++i) {
                float4 kv = kk[lane + i * 32];
                float4 qv = qq[lane + i * 32];
                acc += kv.x * qv.x + kv.y * qv.y + kv.z * qv.z + kv.w * qv.w;
            }
        }
        // warp reduce
        #pragma unroll
        for (int off = 16; off > 0; off >>= 1)
            acc += __shfl_down_sync(0xffffffffu, acc, off);
        if (lane == 0) {
            s_score[w] = (pos >= 0) ? (acc * inv_sqrt_h + s_logw[w]) : -INFINITY;
        }
    }
    __syncthreads();

    // --- stage 4: softmax over 49 (warp 0) ---
    if (wid == 0) {
        float v0 = (lane < W2)      ? s_score[lane]      : -INFINITY;
        float v1 = (lane + 32 < W2) ? s_score[lane + 32] : -INFINITY;
        float m = fmaxf(v0, v1);
        #pragma unroll
        for (int off = 16; off > 0; off >>= 1)
            m = fmaxf(m, __shfl_xor_sync(0xffffffffu, m, off));
        float e0 = (v0 == -INFINITY) ? 0.0f : __expf(v0 - m);
        float e1 = (v1 == -INFINITY) ? 0.0f : __expf(v1 - m);
        float ssum = e0 + e1;
        #pragma unroll
        for (int off = 16; off > 0; off >>= 1)
            ssum += __shfl_xor_sync(0xffffffffu, ssum, off);
        float inv = 1.0f / ssum;
        if (lane < W2)      s_attn[lane]      = e0 * inv;
        if (lane + 32 < W2) s_attn[lane + 32] = e1 * inv;
    }
    __syncthreads();

    // --- stage 5: output. Each thread owns one hidden index ---
    const float* vb = v + (size_t)b * S * HIDDEN;
    float acc = 0.0f;
    #pragma unroll 7
    for (int w = 0; w < W2; ++w) {
        int pos = s_pos[w];
        if (pos >= 0) {
            acc += s_attn[w] * __ldg(vb + (size_t)pos * HIDDEN + tid);
        }
    }
    out[(size_t)b * HIDDEN + tid] = acc;
}

extern "C" void kernel_launch(void* const* d_in, const int* in_sizes, int n_in,
                              void* d_out, int out_size)
{
    const float* q       = (const float*)d_in[0];
    const float* k       = (const float*)d_in[1];
    const float* v       = (const float*)d_in[2];
    const int*   qpos    = (const int*)d_in[3];
    const float* dscale  = (const float*)d_in[4];
    const float* lbias   = (const float*)d_in[5];
    const int*   hcoords = (const int*)d_in[6];
    const int*   hinv    = (const int*)d_in[7];
    float*       out     = (float*)d_out;

    int B = in_sizes[3];                      // 128
    int H = in_sizes[0] / B;                  // 512
    int S = in_sizes[1] / (B * H);            // 4096
    int inv_elems = in_sizes[7];              // grid*grid
    int grid_n = 1;
    while (grid_n * grid_n < inv_elems) grid_n <<= 1;  // 256

    hilbert_attn_kernel<<<B, NTHREADS>>>(q, k, v, qpos, dscale, lbias,
                                         hcoords, hinv, out, S, grid_n);
}

// round 3
// speedup vs baseline: 1.9143x; 1.9143x over previous
#include <cuda_runtime.h>
#include <math.h>

// BATCH=128, SEQ_LEN=4096, HIDDEN=512, WINDOW=7 (W2=49), GRID=256
#define HIDDEN   512
#define WINDOW   7
#define W2       (WINDOW * WINDOW)
#define NTHREADS 512
#define NWARPS   (NTHREADS / 32)

__global__ __launch_bounds__(NTHREADS)
void hilbert_attn_kernel(const float* __restrict__ q,      // (B,1,H)
                         const float* __restrict__ k,      // (B,S,H)
                         const float* __restrict__ v,      // (B,S,H)
                         const int*   __restrict__ qpos,   // (B,)
                         const float* __restrict__ dscale, // ()
                         const float* __restrict__ lbias,  // (W2,)
                         const int*   __restrict__ hcoords,// (MAX_SEQ,2)
                         const int*   __restrict__ hinv,   // (GRID,GRID)
                         float*       __restrict__ out,    // (B,H)
                         int S, int grid_n)
{
    const int b    = blockIdx.x;
    const int tid  = threadIdx.x;
    const int wid  = tid >> 5;
    const int lane = tid & 31;

    // float4-typed: guaranteed 16B alignment (R2 crash was a misaligned
    // reinterpret_cast on a float-typed smem array).
    __shared__ float4   s_part[NWARPS * HIDDEN / 4];   // 32 KB
    __shared__ float    s_lbias[W2];
    __shared__ int      s_pos[W2];
    __shared__ float    s_logw[W2];
    __shared__ unsigned s_mask[2];
    __shared__ int      s_q2d[2];
    __shared__ float    s_esum[NWARPS];

    // ---- q into registers: thread covers h = c*128 + lane*4 .. +3 ----
    float4 qv[4];
    {
        const float4* qg = reinterpret_cast<const float4*>(q + (size_t)b * HIDDEN);
        #pragma unroll
        for (int c = 0; c < 4; ++c) qv[c] = qg[c * 32 + lane];
    }

    if (tid == 0) {
        int p = qpos[b];
        s_q2d[0] = hcoords[2 * p];
        s_q2d[1] = hcoords[2 * p + 1];
    }
    if (tid < W2) s_lbias[tid] = lbias[tid];
    if (tid < 2)  s_mask[tid]  = 0u;
    __syncthreads();

    // ---- neighbor positions (parallel) + validity bitmask ----
    if (tid < W2) {
        int dx = tid / WINDOW - (WINDOW / 2);
        int dy = tid % WINDOW - (WINDOW / 2);
        int nx = s_q2d[0] + dx;
        int ny = s_q2d[1] + dy;
        bool ing = (nx >= 0) & (nx < grid_n) & (ny >= 0) & (ny < grid_n);
        int pos = ing ? hinv[nx * grid_n + ny] : -1;
        bool valid = ing && (pos >= 0) && (pos < S);
        s_pos[tid] = valid ? pos : -1;
        if (valid) atomicOr(&s_mask[tid >> 5], 1u << (tid & 31));
    }
    __syncthreads();

    // ---- compacted-bias index via popc + log weight (parallel) ----
    if (tid < W2 && s_pos[tid] >= 0) {
        unsigned m0 = s_mask[0], m1 = s_mask[1];
        int c;
        if (tid < 32) {
            unsigned mm = (tid == 31) ? 0xffffffffu : ((2u << tid) - 1u);
            c = __popc(m0 & mm) - 1;
        } else {
            unsigned mm = (2u << (tid - 32)) - 1u;
            c = __popc(m0) + __popc(m1 & mm) - 1;
        }
        int dx = tid / WINDOW - (WINDOW / 2);
        int dy = tid % WINDOW - (WINDOW / 2);
        float dist = (float)(abs(dx) + abs(dy));
        float ww = __expf(-dist * dscale[0]) + s_lbias[c];
        s_logw[tid] = logf(ww + 1e-8f);
    }
    __syncthreads();

    // ---- fused score + weighted-V accumulation per warp ----
    const float inv_sqrt_h = 0.04419417382415922f; // 1/sqrt(512)
    const float* kb = k + (size_t)b * S * HIDDEN;
    const float* vb = v + (size_t)b * S * HIDDEN;

    float4 acc[4];
    #pragma unroll
    for (int c = 0; c < 4; ++c) acc[c] = make_float4(0.f, 0.f, 0.f, 0.f);
    float esum = 0.0f;

    for (int w = wid; w < W2; w += NWARPS) {
        int pos = s_pos[w];
        if (pos < 0) continue;
        const float4* kr = reinterpret_cast<const float4*>(kb + (size_t)pos * HIDDEN);
        const float4* vr = reinterpret_cast<const float4*>(vb + (size_t)pos * HIDDEN);

        float4 kk4[4], vv4[4];
        #pragma unroll
        for (int c = 0; c < 4; ++c) kk4[c] = kr[c * 32 + lane];
        #pragma unroll
        for (int c = 0; c < 4; ++c) vv4[c] = vr[c * 32 + lane];

        float d = 0.0f;
        #pragma unroll
        for (int c = 0; c < 4; ++c)
            d += kk4[c].x * qv[c].x + kk4[c].y * qv[c].y
               + kk4[c].z * qv[c].z + kk4[c].w * qv[c].w;
        #pragma unroll
        for (int off = 16; off > 0; off >>= 1)
            d += __shfl_xor_sync(0xffffffffu, d, off);

        // unnormalized exp weight (scores bounded, safe in fp32)
        float e = __expf(d * inv_sqrt_h + s_logw[w]);
        esum += e;

        #pragma unroll
        for (int c = 0; c < 4; ++c) {
            acc[c].x += e * vv4[c].x;
            acc[c].y += e * vv4[c].y;
            acc[c].z += e * vv4[c].z;
            acc[c].w += e * vv4[c].w;
        }
    }

    // ---- cross-warp reduction ----
    {
        float4* sp = &s_part[wid * (HIDDEN / 4)];
        #pragma unroll
        for (int c = 0; c < 4; ++c) sp[c * 32 + lane] = acc[c];
        if (lane == 0) s_esum[wid] = esum;
    }
    __syncthreads();

    const float* s_part_f = reinterpret_cast<const float*>(s_part);
    float num = 0.0f;
    #pragma unroll
    for (int ww = 0; ww < NWARPS; ++ww) num += s_part_f[ww * HIDDEN + tid];
    float den = 0.0f;
    #pragma unroll
    for (int ww = 0; ww < NWARPS; ++ww) den += s_esum[ww];

    out[(size_t)b * HIDDEN + tid] = num / den;
}

extern "C" void kernel_launch(void* const* d_in, const int* in_sizes, int n_in,
                              void* d_out, int out_size)
{
    const float* q       = (const float*)d_in[0];
    const float* k       = (const float*)d_in[1];
    const float* v       = (const float*)d_in[2];
    const int*   qpos    = (const int*)d_in[3];
    const float* dscale  = (const float*)d_in[4];
    const float* lbias   = (const float*)d_in[5];
    const int*   hcoords = (const int*)d_in[6];
    const int*   hinv    = (const int*)d_in[7];
    float*       out     = (float*)d_out;

    int B = in_sizes[3];                      // 128
    int H = in_sizes[0] / B;                  // 512
    int S = in_sizes[1] / (B * H);            // 4096
    int inv_elems = in_sizes[7];              // grid*grid
    int grid_n = 1;
    while (grid_n * grid_n < inv_elems) grid_n <<= 1;  // 256

    hilbert_attn_kernel<<<B, NTHREADS>>>(q, k, v, qpos, dscale, lbias,
                                         hcoords, hinv, out, S, grid_n);
}